// round 9
// baseline (speedup 1.0000x reference)
#include <cuda_runtime.h>
#include <cuda_bf16.h>

#define NN 50000
#define NE 600000
#define CC 128
#define NG 64
#define EPSV 1e-5f
#define NB 196      // ceil(NN/256)
#define AGB 6250    // NN/8 aggregate blocks
#define SBLK 200    // stats grid

// ---------------- scratch (device globals; zero-initialized .bss) -----------
__device__ unsigned int g_hb[NN * 64];    // GEMM out, bf16x2 (2 ch / uint)
__device__ unsigned int g_aggb[NN * 64];  // aggregated messages, bf16x2
__device__ int   g_degi[NN];              // zeroed by scan1 after use
__device__ float g_dinv[NN];
__device__ int   g_off[NN + 1];
__device__ int   g_cursor[NN];            // zeroed by pool_head after use
__device__ int   g_bsum[256];
__device__ int2  g_edge[NE];              // CSR payload: {src, f32bits(weight)}
__device__ float g_psum[SBLK * CC];
__device__ float g_psq[SBLK * CC];
__device__ float g_scale[CC];
__device__ float g_shift[CC];
__device__ int   g_cnt = 0;               // stats last-block counter

// ---------------- packed f32x2 helpers (sm_103a) ----------------
__device__ __forceinline__ unsigned long long bcast2(float x) {
    unsigned long long r;
    asm("mov.b64 %0, {%1, %1};" : "=l"(r) : "f"(x));
    return r;
}
__device__ __forceinline__ void fma2(unsigned long long& d,
                                     unsigned long long a,
                                     unsigned long long b) {
    asm("fma.rn.f32x2 %0, %1, %2, %0;" : "+l"(d) : "l"(a), "l"(b));
}
union U64F2 { unsigned long long u; float2 f; };

// per-block edge_index dtype detection: thread 0 reads 16 interleaved high
// words (int64 little-endian: all zero for values < 2^31; int32 random data
// in [0,NN): false-positive prob ~(1/NN)^16 ~ 0). Identical answer in every
// block -> no cross-block dependency. Caller passes an smem int.
__device__ __forceinline__ int detect_is64(const int* ei32, int* sflag) {
    if (threadIdx.x == 0) {
        int z = 1;
        #pragma unroll
        for (int k = 0; k < 16; k++)
            if (ei32[2 * k + 1] != 0) z = 0;
        *sflag = z;
    }
    __syncthreads();
    return *sflag;
}

// ---------------- degree count (g_degi starts zero; scan1 re-zeros) ---------
__global__ void prep_kernel(const void* ei_raw) {
    __shared__ int sflag;
    int is64 = detect_is64((const int*)ei_raw, &sflag);
    int e = blockIdx.x * blockDim.x + threadIdx.x;
    if (e >= NE) return;
    int d;
    if (is64) d = (int)((const long long*)ei_raw)[NE + e];
    else      d = ((const int*)ei_raw)[NE + e];
    atomicAdd(&g_degi[d], 1);
}

// ---------------- CSR build: scan (dinv fused; self-cleaning degi) ----------
__global__ void scan1_kernel() {
    __shared__ int sh[256];
    int t = threadIdx.x;
    int i = blockIdx.x * 256 + t;
    int v = (i < NN) ? g_degi[i] : 0;
    if (i < NN) {
        g_dinv[i] = (v > 0) ? rsqrtf((float)v) : 0.0f;
        g_degi[i] = 0;                     // reset for next replay
    }
    sh[t] = v;
    __syncthreads();
    #pragma unroll
    for (int off = 1; off < 256; off <<= 1) {
        int tmp = (t >= off) ? sh[t - off] : 0;
        __syncthreads();
        sh[t] += tmp;
        __syncthreads();
    }
    if (i < NN) g_off[i] = sh[t] - v;      // exclusive within block
    if (t == 255) g_bsum[blockIdx.x] = sh[255];
}

// every block redundantly scans the 196 block sums (cheap), adds its base
__global__ void scan23_kernel() {
    __shared__ int sh[256];
    int t = threadIdx.x;
    int v = (t < NB) ? g_bsum[t] : 0;
    sh[t] = v;
    __syncthreads();
    #pragma unroll
    for (int off = 1; off < 256; off <<= 1) {
        int tmp = (t >= off) ? sh[t - off] : 0;
        __syncthreads();
        sh[t] += tmp;
        __syncthreads();
    }
    int base = (blockIdx.x == 0) ? 0 : sh[blockIdx.x - 1];  // exclusive prefix
    int i = blockIdx.x * 256 + t;
    if (i < NN) g_off[i] += base;
    if (i == 0) g_off[NN] = NE;
}

// fill CSR slots; weight dinv[s]*dinv[d] inline (g_cursor starts zero)
__global__ void fill_kernel(const void* ei_raw) {
    __shared__ int sflag;
    int is64 = detect_is64((const int*)ei_raw, &sflag);
    int e = blockIdx.x * blockDim.x + threadIdx.x;
    if (e >= NE) return;
    int s, d;
    if (is64) {
        const long long* p = (const long long*)ei_raw;
        s = (int)p[e]; d = (int)p[NE + e];
    } else {
        const int* p = (const int*)ei_raw;
        s = p[e]; d = p[NE + e];
    }
    float w = g_dinv[s] * g_dinv[d];
    int p2 = atomicAdd(&g_cursor[d], 1);
    g_edge[g_off[d] + p2] = make_int2(s, __float_as_int(w));
}

// ---------------- GEMM: [NN,128] @ [128,128] -> g_hb (bf16x2) ---------------
// fuse==1: A = relu(bf16(g_aggb) * g_scale + g_shift) inline on load.
// fuse==0: A = Xext (raw fp32 input features).
__global__ void __launch_bounds__(256) gemm_kernel(const float* __restrict__ Xext,
                                                   const float* __restrict__ W,
                                                   int fuse) {
    __shared__ __align__(16) float Ws[16][128];
    __shared__ __align__(16) float As[16][132];  // 528B row stride (16B mult)
    int tid = threadIdx.x;
    int m0 = blockIdx.x * 128;
    int tx = tid & 15, ty = tid >> 4;

    unsigned long long acc2[8][4];
    #pragma unroll
    for (int i = 0; i < 8; i++)
        #pragma unroll
        for (int j = 0; j < 4; j++) acc2[i][j] = 0ULL;  // {+0.f, +0.f}

    for (int kk = 0; kk < 128; kk += 16) {
        #pragma unroll
        for (int p = 0; p < 2; p++) {
            int f = tid * 2 + p;
            int k = f >> 5, n4 = f & 31;
            ((float4*)Ws[k])[n4] = ((const float4*)W)[(kk + k) * 32 + n4];
        }
        #pragma unroll
        for (int p = 0; p < 2; p++) {
            int f = tid * 2 + p;
            int r = f >> 2, c4 = f & 3;
            int row = m0 + r;
            int col = kk + c4 * 4;
            float4 v = make_float4(0.f, 0.f, 0.f, 0.f);
            if (row < NN) {
                if (fuse) {
                    uint2 pq = *(const uint2*)(g_aggb + row * 64 + (col >> 1));
                    float2 f01 = __bfloat1622float2(*(__nv_bfloat162*)&pq.x);
                    float2 f23 = __bfloat1622float2(*(__nv_bfloat162*)&pq.y);
                    float4 sc = *(const float4*)(g_scale + col);
                    float4 sh = *(const float4*)(g_shift + col);
                    v.x = fmaxf(fmaf(f01.x, sc.x, sh.x), 0.f);
                    v.y = fmaxf(fmaf(f01.y, sc.y, sh.y), 0.f);
                    v.z = fmaxf(fmaf(f23.x, sc.z, sh.z), 0.f);
                    v.w = fmaxf(fmaf(f23.y, sc.w, sh.w), 0.f);
                } else {
                    v = *(const float4*)(Xext + row * CC + col);
                }
            }
            As[c4 * 4 + 0][r] = v.x;
            As[c4 * 4 + 1][r] = v.y;
            As[c4 * 4 + 2][r] = v.z;
            As[c4 * 4 + 3][r] = v.w;
        }
        __syncthreads();
        #pragma unroll
        for (int k = 0; k < 16; k++) {
            float a[8];
            unsigned long long bb[4];
            *(float4*)(a)     = *(float4*)&As[k][ty * 4];
            *(float4*)(a + 4) = *(float4*)&As[k][64 + ty * 4];
            {
                ulonglong2 t0 = *(ulonglong2*)&Ws[k][tx * 4];
                ulonglong2 t1 = *(ulonglong2*)&Ws[k][64 + tx * 4];
                bb[0] = t0.x; bb[1] = t0.y; bb[2] = t1.x; bb[3] = t1.y;
            }
            #pragma unroll
            for (int i = 0; i < 8; i++) {
                unsigned long long ai = bcast2(a[i]);
                fma2(acc2[i][0], ai, bb[0]);
                fma2(acc2[i][1], ai, bb[1]);
                fma2(acc2[i][2], ai, bb[2]);
                fma2(acc2[i][3], ai, bb[3]);
            }
        }
        __syncthreads();
    }
    #pragma unroll
    for (int i = 0; i < 8; i++) {
        int row = m0 + ((i < 4) ? (ty * 4 + i) : (64 + ty * 4 + (i - 4)));
        if (row < NN) {
            U64F2 p0, p1, p2, p3;
            p0.u = acc2[i][0]; p1.u = acc2[i][1];
            p2.u = acc2[i][2]; p3.u = acc2[i][3];
            __nv_bfloat162 b0 = __floats2bfloat162_rn(p0.f.x, p0.f.y);
            __nv_bfloat162 b1 = __floats2bfloat162_rn(p1.f.x, p1.f.y);
            __nv_bfloat162 b2 = __floats2bfloat162_rn(p2.f.x, p2.f.y);
            __nv_bfloat162 b3 = __floats2bfloat162_rn(p3.f.x, p3.f.y);
            unsigned int u0 = *(unsigned int*)&b0;
            unsigned int u1 = *(unsigned int*)&b1;
            unsigned int u2 = *(unsigned int*)&b2;
            unsigned int u3 = *(unsigned int*)&b3;
            *(uint2*)(g_hb + row * 64 + tx * 2)      = make_uint2(u0, u1);
            *(uint2*)(g_hb + row * 64 + 32 + tx * 2) = make_uint2(u2, u3);
        }
    }
}

// ---------------- gather aggregation (bf16 in, bf16 out; unroll x4) ---------
// 64 threads/node, 2 channels each; 8 nodes per 512-thr block; grid = AGB.
__global__ void __launch_bounds__(512) aggregate_kernel() {
    int node = blockIdx.x * 8 + (threadIdx.x >> 6);   // grid exact: AGB*8 == NN
    int c = threadIdx.x & 63;
    int s = g_off[node], e = g_off[node + 1];
    float ax0 = 0.f, ay0 = 0.f, ax1 = 0.f, ay1 = 0.f;
    float ax2 = 0.f, ay2 = 0.f, ax3 = 0.f, ay3 = 0.f;
    int j = s;
    for (; j + 3 < e; j += 4) {
        int2 e0 = g_edge[j];
        int2 e1 = g_edge[j + 1];
        int2 e2 = g_edge[j + 2];
        int2 e3 = g_edge[j + 3];
        unsigned int u0 = g_hb[e0.x * 64 + c];
        unsigned int u1 = g_hb[e1.x * 64 + c];
        unsigned int u2 = g_hb[e2.x * 64 + c];
        unsigned int u3 = g_hb[e3.x * 64 + c];
        float2 f0 = __bfloat1622float2(*(__nv_bfloat162*)&u0);
        float2 f1 = __bfloat1622float2(*(__nv_bfloat162*)&u1);
        float2 f2 = __bfloat1622float2(*(__nv_bfloat162*)&u2);
        float2 f3 = __bfloat1622float2(*(__nv_bfloat162*)&u3);
        float w0 = __int_as_float(e0.y);
        float w1 = __int_as_float(e1.y);
        float w2 = __int_as_float(e2.y);
        float w3 = __int_as_float(e3.y);
        ax0 += w0 * f0.x; ay0 += w0 * f0.y;
        ax1 += w1 * f1.x; ay1 += w1 * f1.y;
        ax2 += w2 * f2.x; ay2 += w2 * f2.y;
        ax3 += w3 * f3.x; ay3 += w3 * f3.y;
    }
    for (; j < e; j++) {
        int2 e0 = g_edge[j];
        unsigned int u0 = g_hb[e0.x * 64 + c];
        float2 f0 = __bfloat1622float2(*(__nv_bfloat162*)&u0);
        float w0 = __int_as_float(e0.y);
        ax0 += w0 * f0.x; ay0 += w0 * f0.y;
    }
    float r0 = (ax0 + ax1) + (ax2 + ax3);
    float r1 = (ay0 + ay1) + (ay2 + ay3);
    __nv_bfloat162 b = __floats2bfloat162_rn(r0, r1);
    g_aggb[node * 64 + c] = *(unsigned int*)&b;
}

// ---------------- BN stats (bf16 agg) with fused last-block finalize --------
__global__ void __launch_bounds__(256) stats_kernel(const float* __restrict__ gam,
                                                    const float* __restrict__ bet) {
    __shared__ float4 sacc[256];   // {sum_x, sumsq_x, sum_y, sumsq_y}
    __shared__ int slast;
    int t = threadIdx.x;
    int u = t & 63;     // uint column (channels 2u, 2u+1)
    int sub = t >> 6;   // 0..3
    const int rpb = (NN + SBLK - 1) / SBLK;  // 250
    int r0 = blockIdx.x * rpb;
    int r1 = min(NN, r0 + rpb);
    float sx = 0.f, qx = 0.f, sy = 0.f, qy = 0.f;
    for (int r = r0 + sub; r < r1; r += 4) {
        unsigned int w = g_aggb[r * 64 + u];
        float2 f = __bfloat1622float2(*(__nv_bfloat162*)&w);
        sx += f.x; qx += f.x * f.x;
        sy += f.y; qy += f.y * f.y;
    }
    sacc[t] = make_float4(sx, qx, sy, qy);
    __syncthreads();
    if (t < 64) {
        float4 a0 = sacc[t], a1 = sacc[t + 64], a2 = sacc[t + 128], a3 = sacc[t + 192];
        g_psum[blockIdx.x * CC + 2 * t]     = (a0.x + a1.x) + (a2.x + a3.x);
        g_psq [blockIdx.x * CC + 2 * t]     = (a0.y + a1.y) + (a2.y + a3.y);
        g_psum[blockIdx.x * CC + 2 * t + 1] = (a0.z + a1.z) + (a2.z + a3.z);
        g_psq [blockIdx.x * CC + 2 * t + 1] = (a0.w + a1.w) + (a2.w + a3.w);
    }
    __threadfence();
    if (t == 0)
        slast = (atomicAdd(&g_cnt, 1) == SBLK - 1) ? 1 : 0;
    __syncthreads();
    if (slast) {
        __threadfence();  // acquire: see all blocks' partials
        if (t < 128) {
            float ts = 0.f, ts2 = 0.f;
            for (int b = 0; b < SBLK; b++) {
                ts  += g_psum[b * CC + t];
                ts2 += g_psq[b * CC + t];
            }
            float mu = ts * (1.0f / NN);
            float var = fmaxf(ts2 * (1.0f / NN) - mu * mu, 0.f);
            float sc = gam[t] * rsqrtf(var + EPSV);
            g_scale[t] = sc;
            g_shift[t] = bet[t] - mu * sc;
        }
        __syncthreads();
        if (t == 0) g_cnt = 0;  // reset for next layer / replay
    }
}

// ---------------- pool + head (layer-3 BN fused; resets g_cursor) -----------
__global__ void __launch_bounds__(512) pool_head_kernel(const void* batch_raw,
                                                        const float* __restrict__ Wh,
                                                        const float* __restrict__ bh,
                                                        float* __restrict__ out) {
    __shared__ float part[512];
    __shared__ float pooled[CC];
    __shared__ int sb[2];
    int g = blockIdx.x;
    int t = threadIdx.x;
    int c = t & 127;
    int sub = t >> 7;  // 0..3
    if (t < 2) {
        // batch dtype: sorted, head all zeros -> detect from the tail. Word
        // [NN-1] readable under either width; int64 -> high word of elem
        // 24999 (0) while word [NN-2] (its low word) nonzero w.h.p.; int32 ->
        // batch[NN-1] ~ 63 nonzero w.h.p.
        const int* b32 = (const int*)batch_raw;
        int bis64 = (b32[NN - 1] == 0 && b32[NN - 2] != 0) ? 1 : 0;
        int target = g + t;
        int lo = 0, hi = NN;
        if (bis64) {
            const long long* b = (const long long*)batch_raw;
            while (lo < hi) { int mid = (lo + hi) >> 1; if (b[mid] < (long long)target) lo = mid + 1; else hi = mid; }
        } else {
            while (lo < hi) { int mid = (lo + hi) >> 1; if (b32[mid] < target) lo = mid + 1; else hi = mid; }
        }
        sb[t] = lo;
    }
    __syncthreads();
    int s = sb[0], e = sb[1];
    float sc = g_scale[c], sh = g_shift[c];
    float a = 0.f;
    for (int r = s + sub; r < e; r += 4) {
        unsigned int w = g_aggb[r * 64 + (c >> 1)];
        float2 f = __bfloat1622float2(*(__nv_bfloat162*)&w);
        float v = (c & 1) ? f.y : f.x;
        a += fmaxf(fmaf(v, sc, sh), 0.f);
    }
    part[t] = a;
    __syncthreads();
    if (t < 128) {
        float cnt = (float)(e - s);
        pooled[t] = (part[t] + part[t + 128] + part[t + 256] + part[t + 384])
                    / fmaxf(cnt, 1.0f);
    }
    __syncthreads();
    if (t < 8) {
        float o = bh[t];
        #pragma unroll 8
        for (int k = 0; k < CC; k++) o += pooled[k] * Wh[k * 8 + t];
        out[g * 8 + t] = o;
    }
    // reset CSR cursor for the next replay (graph-capture determinism)
    for (int i = g * 512 + t; i < NN; i += NG * 512) g_cursor[i] = 0;
}

// ---------------- launch ----------------
extern "C" void kernel_launch(void* const* d_in, const int* in_sizes, int n_in,
                              void* d_out, int out_size) {
    const float* x  = (const float*)d_in[0];
    const void*  ei = d_in[1];
    const void*  batch = d_in[2];
    const float* W[3]  = { (const float*)d_in[3],  (const float*)d_in[7],  (const float*)d_in[11] };
    const float* gg[3] = { (const float*)d_in[5],  (const float*)d_in[9],  (const float*)d_in[13] };
    const float* be[3] = { (const float*)d_in[6],  (const float*)d_in[10], (const float*)d_in[14] };
    const float* Wh = (const float*)d_in[15];
    const float* bh = (const float*)d_in[16];
    float* out = (float*)d_out;

    const int EB = (NE + 255) / 256;   // 2344

    prep_kernel<<<EB, 256>>>(ei);
    scan1_kernel<<<NB, 256>>>();
    scan23_kernel<<<NB, 256>>>();
    fill_kernel<<<EB, 256>>>(ei);

    for (int l = 0; l < 3; l++) {
        gemm_kernel<<<(NN + 127) / 128, 256>>>(x, W[l], l == 0 ? 0 : 1);
        aggregate_kernel<<<AGB, 512>>>();
        stats_kernel<<<SBLK, 256>>>(gg[l], be[l]);
    }

    pool_head_kernel<<<NG, 512>>>(batch, Wh, bh, out);
}

// round 10
// speedup vs baseline: 1.3896x; 1.3896x over previous
#include <cuda_runtime.h>
#include <cuda_bf16.h>

#define NN 50000
#define NE 600000
#define CC 128
#define NG 64
#define EPSV 1e-5f
#define NB 196      // ceil(NN/256)
#define AGB 6250    // NN/8 aggregate blocks
#define SBLK 200    // stats grid
#define GEMM_SMEM (2 * 128 * 68 * 4)   // As + Wt, 68 words/row (8-bf16 pad)

// ---------------- scratch (device globals; zero-initialized .bss) -----------
__device__ unsigned int g_hb[NN * 64];   // GEMM out, bf16x2 (2 ch / uint)
__device__ float g_agg[NN * CC];         // aggregated messages (pre-BN), fp32
__device__ int   g_degi[NN];             // zeroed by scan1 after use
__device__ float g_dinv[NN];
__device__ int   g_off[NN + 1];
__device__ int   g_cursor[NN];           // zeroed by pool_head after use
__device__ int   g_bsum[256];
__device__ int2  g_edge[NE];             // CSR payload: {src, f32bits(weight)}
__device__ float g_psum[SBLK * CC];
__device__ float g_psq[SBLK * CC];
__device__ float g_scale[CC];
__device__ float g_shift[CC];
__device__ int   g_cnt = 0;              // stats last-block counter

// per-block edge_index dtype detection (int64 little-endian: interleaved high
// words all zero for values < 2^31; int32 random in [0,NN): false-positive
// prob ~(1/NN)^16 ~ 0). Identical answer every block.
__device__ __forceinline__ int detect_is64(const int* ei32, int* sflag) {
    if (threadIdx.x == 0) {
        int z = 1;
        #pragma unroll
        for (int k = 0; k < 16; k++)
            if (ei32[2 * k + 1] != 0) z = 0;
        *sflag = z;
    }
    __syncthreads();
    return *sflag;
}

// ---------------- degree count (g_degi starts zero; scan1 re-zeros) ---------
__global__ void prep_kernel(const void* ei_raw) {
    __shared__ int sflag;
    int is64 = detect_is64((const int*)ei_raw, &sflag);
    int e = blockIdx.x * blockDim.x + threadIdx.x;
    if (e >= NE) return;
    int d;
    if (is64) d = (int)((const long long*)ei_raw)[NE + e];
    else      d = ((const int*)ei_raw)[NE + e];
    atomicAdd(&g_degi[d], 1);
}

// ---------------- CSR build: scan (dinv fused; self-cleaning degi) ----------
__global__ void scan1_kernel() {
    __shared__ int sh[256];
    int t = threadIdx.x;
    int i = blockIdx.x * 256 + t;
    int v = (i < NN) ? g_degi[i] : 0;
    if (i < NN) {
        g_dinv[i] = (v > 0) ? rsqrtf((float)v) : 0.0f;
        g_degi[i] = 0;                     // reset for next replay
    }
    sh[t] = v;
    __syncthreads();
    #pragma unroll
    for (int off = 1; off < 256; off <<= 1) {
        int tmp = (t >= off) ? sh[t - off] : 0;
        __syncthreads();
        sh[t] += tmp;
        __syncthreads();
    }
    if (i < NN) g_off[i] = sh[t] - v;      // exclusive within block
    if (t == 255) g_bsum[blockIdx.x] = sh[255];
}

__global__ void scan23_kernel() {
    __shared__ int sh[256];
    int t = threadIdx.x;
    int v = (t < NB) ? g_bsum[t] : 0;
    sh[t] = v;
    __syncthreads();
    #pragma unroll
    for (int off = 1; off < 256; off <<= 1) {
        int tmp = (t >= off) ? sh[t - off] : 0;
        __syncthreads();
        sh[t] += tmp;
        __syncthreads();
    }
    int base = (blockIdx.x == 0) ? 0 : sh[blockIdx.x - 1];  // exclusive prefix
    int i = blockIdx.x * 256 + t;
    if (i < NN) g_off[i] += base;
    if (i == 0) g_off[NN] = NE;
}

__global__ void fill_kernel(const void* ei_raw) {
    __shared__ int sflag;
    int is64 = detect_is64((const int*)ei_raw, &sflag);
    int e = blockIdx.x * blockDim.x + threadIdx.x;
    if (e >= NE) return;
    int s, d;
    if (is64) {
        const long long* p = (const long long*)ei_raw;
        s = (int)p[e]; d = (int)p[NE + e];
    } else {
        const int* p = (const int*)ei_raw;
        s = p[e]; d = p[NE + e];
    }
    float w = g_dinv[s] * g_dinv[d];
    int p2 = atomicAdd(&g_cursor[d], 1);
    g_edge[g_off[d] + p2] = make_int2(s, __float_as_int(w));
}

// ---------------- tensor-core GEMM: [NN,128] @ [128,128] -> g_hb ------------
// mma.sync.m16n8k16 bf16 x bf16 -> f32. Block tile 128x128, K=128 fully
// smem-resident. 8 warps: warpM = w>>1 (32 M-rows), warpN = w&1 (64 N-cols).
// fuse==1: A = relu(g_agg * g_scale + g_shift) (fp32->BN->bf16 on load).
// fuse==0: A = Xext fp32 -> bf16.
__device__ __forceinline__ void mma16816(float* d, const unsigned int* a,
                                         unsigned int b0, unsigned int b1) {
    asm volatile(
        "mma.sync.aligned.m16n8k16.row.col.f32.bf16.bf16.f32 "
        "{%0,%1,%2,%3}, {%4,%5,%6,%7}, {%8,%9}, {%0,%1,%2,%3};\n"
        : "+f"(d[0]), "+f"(d[1]), "+f"(d[2]), "+f"(d[3])
        : "r"(a[0]), "r"(a[1]), "r"(a[2]), "r"(a[3]), "r"(b0), "r"(b1));
}

__global__ void __launch_bounds__(256) gemm_kernel(const float* __restrict__ Xext,
                                                   const float* __restrict__ W,
                                                   int fuse) {
    extern __shared__ unsigned int smem_u[];
    unsigned int* As = smem_u;              // [128 rows][68 words] bf16x2, k-pairs
    unsigned int* Wt = smem_u + 128 * 68;   // [128 n-rows][68 words] k-pairs
    int tid = threadIdx.x;
    int m0 = blockIdx.x * 128;

    // Wt load: item = (kp, n); W[2kp][n], W[2kp+1][n] -> bf16x2 at Wt[n][kp].
    // Global coalesced (consecutive n); smem ST 4-way conflict (acceptable).
    #pragma unroll 4
    for (int it = 0; it < 32; it++) {
        int item = tid + 256 * it;          // 8192 items: kp = item>>7, n = item&127
        int n = item & 127, kp = item >> 7;
        float w0 = W[(2 * kp) * 128 + n];
        float w1 = W[(2 * kp + 1) * 128 + n];
        __nv_bfloat162 b = __floats2bfloat162_rn(w0, w1);
        Wt[n * 68 + kp] = *(unsigned int*)&b;
    }
    // A load: float4 per item, BN+ReLU if fuse, -> 2 bf16x2 words. Conflict-free.
    const float* Abase = fuse ? (const float*)g_agg : Xext;
    #pragma unroll 4
    for (int it = 0; it < 16; it++) {
        int f = tid + 256 * it;             // 4096 float4 items
        int row = f >> 5, c4 = f & 31;
        int grow = m0 + row;
        float4 v = make_float4(0.f, 0.f, 0.f, 0.f);
        if (grow < NN) {
            v = *(const float4*)(Abase + grow * CC + c4 * 4);
            if (fuse) {
                float4 sc = *(const float4*)(g_scale + c4 * 4);
                float4 sh = *(const float4*)(g_shift + c4 * 4);
                v.x = fmaxf(fmaf(v.x, sc.x, sh.x), 0.f);
                v.y = fmaxf(fmaf(v.y, sc.y, sh.y), 0.f);
                v.z = fmaxf(fmaf(v.z, sc.z, sh.z), 0.f);
                v.w = fmaxf(fmaf(v.w, sc.w, sh.w), 0.f);
            }
        }
        __nv_bfloat162 p0 = __floats2bfloat162_rn(v.x, v.y);
        __nv_bfloat162 p1 = __floats2bfloat162_rn(v.z, v.w);
        As[row * 68 + c4 * 2]     = *(unsigned int*)&p0;
        As[row * 68 + c4 * 2 + 1] = *(unsigned int*)&p1;
    }
    __syncthreads();

    int lane = tid & 31;
    int w = tid >> 5;
    int warpM = w >> 1, warpN = w & 1;
    int rq = lane >> 2, lq = lane & 3;      // quad row / pair col

    float acc[2][8][4];
    #pragma unroll
    for (int ma = 0; ma < 2; ma++)
        #pragma unroll
        for (int na = 0; na < 8; na++)
            #pragma unroll
            for (int q = 0; q < 4; q++) acc[ma][na][q] = 0.f;

    #pragma unroll
    for (int k0 = 0; k0 < 8; k0++) {        // 16-wide k steps
        int cp = k0 * 8 + lq;
        unsigned int a[2][4];
        #pragma unroll
        for (int ma = 0; ma < 2; ma++) {
            int r = warpM * 32 + ma * 16 + rq;
            a[ma][0] = As[r * 68 + cp];
            a[ma][1] = As[(r + 8) * 68 + cp];
            a[ma][2] = As[r * 68 + cp + 4];
            a[ma][3] = As[(r + 8) * 68 + cp + 4];
        }
        #pragma unroll
        for (int na = 0; na < 8; na++) {
            int n = warpN * 64 + na * 8 + rq;
            unsigned int b0 = Wt[n * 68 + cp];
            unsigned int b1 = Wt[n * 68 + cp + 4];
            mma16816(acc[0][na], a[0], b0, b1);
            mma16816(acc[1][na], a[1], b0, b1);
        }
    }

    // epilogue: f32 accum -> bf16x2 -> g_hb (rows r, r+8; cols quad-coalesced)
    #pragma unroll
    for (int ma = 0; ma < 2; ma++) {
        int r = m0 + warpM * 32 + ma * 16 + rq;
        #pragma unroll
        for (int na = 0; na < 8; na++) {
            int cu = warpN * 32 + na * 4 + lq;
            if (r < NN) {
                __nv_bfloat162 p = __floats2bfloat162_rn(acc[ma][na][0], acc[ma][na][1]);
                g_hb[r * 64 + cu] = *(unsigned int*)&p;
            }
            if (r + 8 < NN) {
                __nv_bfloat162 p = __floats2bfloat162_rn(acc[ma][na][2], acc[ma][na][3]);
                g_hb[(r + 8) * 64 + cu] = *(unsigned int*)&p;
            }
        }
    }
}

// ---------------- gather aggregation (bf16 h in, fp32 agg out; R8-proven) ---
__global__ void __launch_bounds__(512) aggregate_kernel() {
    int node = blockIdx.x * 8 + (threadIdx.x >> 6);   // grid exact: AGB*8 == NN
    int c = threadIdx.x & 63;
    int s = g_off[node], e = g_off[node + 1];
    float ax0 = 0.f, ay0 = 0.f, ax1 = 0.f, ay1 = 0.f;
    int j = s;
    for (; j + 1 < e; j += 2) {
        int2 e0 = g_edge[j];
        int2 e1 = g_edge[j + 1];
        unsigned int u0 = g_hb[e0.x * 64 + c];
        unsigned int u1 = g_hb[e1.x * 64 + c];
        float2 f0 = __bfloat1622float2(*(__nv_bfloat162*)&u0);
        float2 f1 = __bfloat1622float2(*(__nv_bfloat162*)&u1);
        float w0 = __int_as_float(e0.y);
        float w1 = __int_as_float(e1.y);
        ax0 += w0 * f0.x; ay0 += w0 * f0.y;
        ax1 += w1 * f1.x; ay1 += w1 * f1.y;
    }
    if (j < e) {
        int2 e0 = g_edge[j];
        unsigned int u0 = g_hb[e0.x * 64 + c];
        float2 f0 = __bfloat1622float2(*(__nv_bfloat162*)&u0);
        float w0 = __int_as_float(e0.y);
        ax0 += w0 * f0.x; ay0 += w0 * f0.y;
    }
    *(float2*)(g_agg + node * CC + 2 * c) = make_float2(ax0 + ax1, ay0 + ay1);
}

// ---------------- BN stats (fp32 agg) with fused last-block finalize --------
__global__ void __launch_bounds__(256) stats_kernel(const float* __restrict__ gam,
                                                    const float* __restrict__ bet) {
    __shared__ float ssum[256];
    __shared__ float ssq[256];
    __shared__ int slast;
    int c = threadIdx.x & 127;
    int sub = threadIdx.x >> 7;  // 0..1
    const int rpb = (NN + SBLK - 1) / SBLK;  // 250
    int r0 = blockIdx.x * rpb;
    int r1 = min(NN, r0 + rpb);
    float s = 0.f, s2 = 0.f;
    for (int r = r0 + sub; r < r1; r += 2) {
        float v = g_agg[r * CC + c];
        s += v; s2 += v * v;
    }
    ssum[threadIdx.x] = s;
    ssq[threadIdx.x] = s2;
    __syncthreads();
    if (threadIdx.x < 128) {
        g_psum[blockIdx.x * CC + c] = ssum[c] + ssum[c + 128];
        g_psq[blockIdx.x * CC + c]  = ssq[c] + ssq[c + 128];
    }
    __threadfence();
    if (threadIdx.x == 0)
        slast = (atomicAdd(&g_cnt, 1) == SBLK - 1) ? 1 : 0;
    __syncthreads();
    if (slast) {
        __threadfence();  // acquire: see all blocks' partials
        if (threadIdx.x < 128) {
            float ts = 0.f, ts2 = 0.f;
            for (int b = 0; b < SBLK; b++) {
                ts  += g_psum[b * CC + threadIdx.x];
                ts2 += g_psq[b * CC + threadIdx.x];
            }
            float mu = ts * (1.0f / NN);
            float var = fmaxf(ts2 * (1.0f / NN) - mu * mu, 0.f);
            float sc = gam[threadIdx.x] * rsqrtf(var + EPSV);
            g_scale[threadIdx.x] = sc;
            g_shift[threadIdx.x] = bet[threadIdx.x] - mu * sc;
        }
        __syncthreads();
        if (threadIdx.x == 0) g_cnt = 0;  // reset for next layer / replay
    }
}

// ---------------- pool + head (layer-3 BN fused; resets g_cursor) -----------
__global__ void __launch_bounds__(512) pool_head_kernel(const void* batch_raw,
                                                        const float* __restrict__ Wh,
                                                        const float* __restrict__ bh,
                                                        float* __restrict__ out) {
    __shared__ float part[512];
    __shared__ float pooled[CC];
    __shared__ int sb[2];
    int g = blockIdx.x;
    int t = threadIdx.x;
    int c = t & 127;
    int sub = t >> 7;  // 0..3
    if (t < 2) {
        // batch dtype from the tail: word [NN-1] readable either width;
        // int64 -> high word of elem 24999 (0) with word [NN-2] nonzero
        // w.h.p.; int32 -> batch[NN-1] ~ 63 nonzero w.h.p.
        const int* b32 = (const int*)batch_raw;
        int bis64 = (b32[NN - 1] == 0 && b32[NN - 2] != 0) ? 1 : 0;
        int target = g + t;
        int lo = 0, hi = NN;
        if (bis64) {
            const long long* b = (const long long*)batch_raw;
            while (lo < hi) { int mid = (lo + hi) >> 1; if (b[mid] < (long long)target) lo = mid + 1; else hi = mid; }
        } else {
            while (lo < hi) { int mid = (lo + hi) >> 1; if (b32[mid] < target) lo = mid + 1; else hi = mid; }
        }
        sb[t] = lo;
    }
    __syncthreads();
    int s = sb[0], e = sb[1];
    float sc = g_scale[c], sh = g_shift[c];
    float a = 0.f;
    for (int r = s + sub; r < e; r += 4)
        a += fmaxf(fmaf(g_agg[r * CC + c], sc, sh), 0.f);
    part[t] = a;
    __syncthreads();
    if (t < 128) {
        float cnt = (float)(e - s);
        pooled[t] = (part[t] + part[t + 128] + part[t + 256] + part[t + 384])
                    / fmaxf(cnt, 1.0f);
    }
    __syncthreads();
    if (t < 8) {
        float o = bh[t];
        #pragma unroll 8
        for (int k = 0; k < CC; k++) o += pooled[k] * Wh[k * 8 + t];
        out[g * 8 + t] = o;
    }
    // reset CSR cursor for the next replay (graph-capture determinism)
    for (int i = g * 512 + t; i < NN; i += NG * 512) g_cursor[i] = 0;
}

// ---------------- launch ----------------
extern "C" void kernel_launch(void* const* d_in, const int* in_sizes, int n_in,
                              void* d_out, int out_size) {
    const float* x  = (const float*)d_in[0];
    const void*  ei = d_in[1];
    const void*  batch = d_in[2];
    const float* W[3]  = { (const float*)d_in[3],  (const float*)d_in[7],  (const float*)d_in[11] };
    const float* gg[3] = { (const float*)d_in[5],  (const float*)d_in[9],  (const float*)d_in[13] };
    const float* be[3] = { (const float*)d_in[6],  (const float*)d_in[10], (const float*)d_in[14] };
    const float* Wh = (const float*)d_in[15];
    const float* bh = (const float*)d_in[16];
    float* out = (float*)d_out;

    const int EB = (NE + 255) / 256;   // 2344

    // allow 69.6 KB dynamic smem for the GEMM (idempotent; capture-safe)
    cudaFuncSetAttribute(gemm_kernel,
                         cudaFuncAttributeMaxDynamicSharedMemorySize, GEMM_SMEM);

    prep_kernel<<<EB, 256>>>(ei);
    scan1_kernel<<<NB, 256>>>();
    scan23_kernel<<<NB, 256>>>();
    fill_kernel<<<EB, 256>>>(ei);

    for (int l = 0; l < 3; l++) {
        gemm_kernel<<<(NN + 127) / 128, 256, GEMM_SMEM>>>(x, W[l], l == 0 ? 0 : 1);
        aggregate_kernel<<<AGB, 512>>>();
        stats_kernel<<<SBLK, 256>>>(gg[l], be[l]);
    }

    pool_head_kernel<<<NG, 512>>>(batch, Wh, bh, out);
}

// round 16
// speedup vs baseline: 1.5439x; 1.1110x over previous
#include <cuda_runtime.h>
#include <cuda_bf16.h>

#define NN 50000
#define NE 600000
#define CC 128
#define NG 64
#define EPSV 1e-5f
#define NB 196      // ceil(NN/256)
#define AGB 6250    // NN/8 aggregate blocks
#define GEMM_SMEM (2 * 128 * 68 * 4)   // As + Wt, 68 words/row (8-bf16 pad)

// ---------------- scratch (device globals; zero-initialized .bss) -----------
__device__ unsigned int g_hb[NN * 64];    // GEMM out, bf16x2 (2 ch / uint)
__device__ unsigned int g_aggb[NN * 64];  // aggregated messages, bf16x2
__device__ int   g_degi[NN];              // zeroed by scan1 after use
__device__ float g_dinv[NN];
__device__ int   g_off[NN + 1];
__device__ int   g_cursor[NN];            // zeroed by pool_head after use
__device__ int   g_bsum[256];
__device__ int2  g_edge[NE];              // CSR payload: {src, f32bits(weight)}
// BN bucket accumulators: [layer][sum bkt 0-31 | sumsq bkt 32-63][128 ch].
// Zeroed by scan1 at the START of each replay (before any aggregate writes,
// after the previous replay's pool_head consumed them) -> no read/reset race.
__device__ float g_bns[3 * 64 * 128];

// per-block edge_index dtype detection (int64 little-endian: interleaved high
// words all zero for values < 2^31; int32 random in [0,NN): false-positive
// prob ~(1/NN)^16 ~ 0). Identical answer every block.
__device__ __forceinline__ int detect_is64(const int* ei32, int* sflag) {
    if (threadIdx.x == 0) {
        int z = 1;
        #pragma unroll
        for (int k = 0; k < 16; k++)
            if (ei32[2 * k + 1] != 0) z = 0;
        *sflag = z;
    }
    __syncthreads();
    return *sflag;
}

// ---------------- degree count (g_degi starts zero; scan1 re-zeros) ---------
__global__ void prep_kernel(const void* ei_raw) {
    __shared__ int sflag;
    int is64 = detect_is64((const int*)ei_raw, &sflag);
    int e = blockIdx.x * blockDim.x + threadIdx.x;
    if (e >= NE) return;
    int d;
    if (is64) d = (int)((const long long*)ei_raw)[NE + e];
    else      d = ((const int*)ei_raw)[NE + e];
    atomicAdd(&g_degi[d], 1);
}

// ---------------- CSR build: scan (dinv fused; zeroes degi + BN buckets) ----
__global__ void scan1_kernel() {
    __shared__ int sh[256];
    int t = threadIdx.x;
    int i = blockIdx.x * 256 + t;
    int v = (i < NN) ? g_degi[i] : 0;
    if (i < NN) {
        g_dinv[i] = (v > 0) ? rsqrtf((float)v) : 0.0f;
        g_degi[i] = 0;                     // reset for next replay
    }
    if (i < 3 * 64 * 128) g_bns[i] = 0.f;  // fresh buckets for this replay
    sh[t] = v;
    __syncthreads();
    #pragma unroll
    for (int off = 1; off < 256; off <<= 1) {
        int tmp = (t >= off) ? sh[t - off] : 0;
        __syncthreads();
        sh[t] += tmp;
        __syncthreads();
    }
    if (i < NN) g_off[i] = sh[t] - v;      // exclusive within block
    if (t == 255) g_bsum[blockIdx.x] = sh[255];
}

__global__ void scan23_kernel() {
    __shared__ int sh[256];
    int t = threadIdx.x;
    int v = (t < NB) ? g_bsum[t] : 0;
    sh[t] = v;
    __syncthreads();
    #pragma unroll
    for (int off = 1; off < 256; off <<= 1) {
        int tmp = (t >= off) ? sh[t - off] : 0;
        __syncthreads();
        sh[t] += tmp;
        __syncthreads();
    }
    int base = (blockIdx.x == 0) ? 0 : sh[blockIdx.x - 1];  // exclusive prefix
    int i = blockIdx.x * 256 + t;
    if (i < NN) g_off[i] += base;
    if (i == 0) g_off[NN] = NE;
}

__global__ void fill_kernel(const void* ei_raw) {
    __shared__ int sflag;
    int is64 = detect_is64((const int*)ei_raw, &sflag);
    int e = blockIdx.x * blockDim.x + threadIdx.x;
    if (e >= NE) return;
    int s, d;
    if (is64) {
        const long long* p = (const long long*)ei_raw;
        s = (int)p[e]; d = (int)p[NE + e];
    } else {
        const int* p = (const int*)ei_raw;
        s = p[e]; d = p[NE + e];
    }
    float w = g_dinv[s] * g_dinv[d];
    int p2 = atomicAdd(&g_cursor[d], 1);
    g_edge[g_off[d] + p2] = make_int2(s, __float_as_int(w));
}

// compute BN scale/shift for layer lm1 from its buckets into smem (redundant
// per block — the scan23 trick). 128 threads participate; callers sync after.
__device__ __forceinline__ void bn_consts(int lm1, const float* gam,
                                          const float* bet,
                                          float* s_sc, float* s_sh) {
    int t = threadIdx.x;
    if (t < 128) {
        float ts = 0.f, ts2 = 0.f;
        #pragma unroll
        for (int b = 0; b < 32; b++) {
            ts  += g_bns[(lm1 * 64 + b) * 128 + t];
            ts2 += g_bns[(lm1 * 64 + 32 + b) * 128 + t];
        }
        float mu = ts * (1.0f / NN);
        float var = fmaxf(ts2 * (1.0f / NN) - mu * mu, 0.f);
        float sc = gam[t] * rsqrtf(var + EPSV);
        s_sc[t] = sc;
        s_sh[t] = bet[t] - mu * sc;
    }
}

// ---------------- tensor-core GEMM: [NN,128] @ [128,128] -> g_hb ------------
// mma.sync.m16n8k16 bf16 x bf16 -> f32. Block tile 128x128, K=128 resident.
// l>0: A = relu(bf16(g_aggb) * scale + shift), BN consts computed inline from
// layer l-1 buckets. l==0: A = Xext fp32 -> bf16.
__device__ __forceinline__ void mma16816(float* d, const unsigned int* a,
                                         unsigned int b0, unsigned int b1) {
    asm volatile(
        "mma.sync.aligned.m16n8k16.row.col.f32.bf16.bf16.f32 "
        "{%0,%1,%2,%3}, {%4,%5,%6,%7}, {%8,%9}, {%0,%1,%2,%3};\n"
        : "+f"(d[0]), "+f"(d[1]), "+f"(d[2]), "+f"(d[3])
        : "r"(a[0]), "r"(a[1]), "r"(a[2]), "r"(a[3]), "r"(b0), "r"(b1));
}

__global__ void __launch_bounds__(256) gemm_kernel(const float* __restrict__ Xext,
                                                   const float* __restrict__ W,
                                                   const float* __restrict__ gam,
                                                   const float* __restrict__ bet,
                                                   int l) {
    extern __shared__ unsigned int smem_u[];
    unsigned int* As = smem_u;              // [128 rows][68 words] bf16x2, k-pairs
    unsigned int* Wt = smem_u + 128 * 68;   // [128 n-rows][68 words] k-pairs
    __shared__ float s_sc[128], s_sh[128];
    int tid = threadIdx.x;
    int m0 = blockIdx.x * 128;

    if (l > 0) bn_consts(l - 1, gam, bet, s_sc, s_sh);

    // Wt load: item = (kp, n); W[2kp][n], W[2kp+1][n] -> bf16x2 at Wt[n][kp].
    #pragma unroll 4
    for (int it = 0; it < 32; it++) {
        int item = tid + 256 * it;          // 8192 items
        int n = item & 127, kp = item >> 7;
        float w0 = W[(2 * kp) * 128 + n];
        float w1 = W[(2 * kp + 1) * 128 + n];
        __nv_bfloat162 b = __floats2bfloat162_rn(w0, w1);
        Wt[n * 68 + kp] = *(unsigned int*)&b;
    }
    __syncthreads();   // s_sc/s_sh ready before A-load uses them

    #pragma unroll 4
    for (int it = 0; it < 16; it++) {
        int f = tid + 256 * it;             // 4096 items (4 channels each)
        int row = f >> 5, c4 = f & 31;
        int grow = m0 + row;
        float4 v = make_float4(0.f, 0.f, 0.f, 0.f);
        if (grow < NN) {
            if (l > 0) {
                uint2 pq = *(const uint2*)(g_aggb + grow * 64 + c4 * 2);
                float2 f01 = __bfloat1622float2(*(__nv_bfloat162*)&pq.x);
                float2 f23 = __bfloat1622float2(*(__nv_bfloat162*)&pq.y);
                int col = c4 * 4;
                v.x = fmaxf(fmaf(f01.x, s_sc[col],     s_sh[col]),     0.f);
                v.y = fmaxf(fmaf(f01.y, s_sc[col + 1], s_sh[col + 1]), 0.f);
                v.z = fmaxf(fmaf(f23.x, s_sc[col + 2], s_sh[col + 2]), 0.f);
                v.w = fmaxf(fmaf(f23.y, s_sc[col + 3], s_sh[col + 3]), 0.f);
            } else {
                v = *(const float4*)(Xext + grow * CC + c4 * 4);
            }
        }
        __nv_bfloat162 p0 = __floats2bfloat162_rn(v.x, v.y);
        __nv_bfloat162 p1 = __floats2bfloat162_rn(v.z, v.w);
        As[row * 68 + c4 * 2]     = *(unsigned int*)&p0;
        As[row * 68 + c4 * 2 + 1] = *(unsigned int*)&p1;
    }
    __syncthreads();

    int lane = tid & 31;
    int w = tid >> 5;
    int warpM = w >> 1, warpN = w & 1;
    int rq = lane >> 2, lq = lane & 3;

    float acc[2][8][4];
    #pragma unroll
    for (int ma = 0; ma < 2; ma++)
        #pragma unroll
        for (int na = 0; na < 8; na++)
            #pragma unroll
            for (int q = 0; q < 4; q++) acc[ma][na][q] = 0.f;

    #pragma unroll
    for (int k0 = 0; k0 < 8; k0++) {
        int cp = k0 * 8 + lq;
        unsigned int a[2][4];
        #pragma unroll
        for (int ma = 0; ma < 2; ma++) {
            int r = warpM * 32 + ma * 16 + rq;
            a[ma][0] = As[r * 68 + cp];
            a[ma][1] = As[(r + 8) * 68 + cp];
            a[ma][2] = As[r * 68 + cp + 4];
            a[ma][3] = As[(r + 8) * 68 + cp + 4];
        }
        #pragma unroll
        for (int na = 0; na < 8; na++) {
            int n = warpN * 64 + na * 8 + rq;
            unsigned int b0 = Wt[n * 68 + cp];
            unsigned int b1 = Wt[n * 68 + cp + 4];
            mma16816(acc[0][na], a[0], b0, b1);
            mma16816(acc[1][na], a[1], b0, b1);
        }
    }

    #pragma unroll
    for (int ma = 0; ma < 2; ma++) {
        int r = m0 + warpM * 32 + ma * 16 + rq;
        #pragma unroll
        for (int na = 0; na < 8; na++) {
            int cu = warpN * 32 + na * 4 + lq;
            if (r < NN) {
                __nv_bfloat162 p = __floats2bfloat162_rn(acc[ma][na][0], acc[ma][na][1]);
                g_hb[r * 64 + cu] = *(unsigned int*)&p;
            }
            if (r + 8 < NN) {
                __nv_bfloat162 p = __floats2bfloat162_rn(acc[ma][na][2], acc[ma][na][3]);
                g_hb[(r + 8) * 64 + cu] = *(unsigned int*)&p;
            }
        }
    }
}

// ---------------- aggregation + bucketed BN partials (no fence) -------------
// 64 threads/node, 2 channels each; 8 nodes per 512-thr block; grid = AGB.
// Tail: smem reduce over the block's 8 nodes, atomicAdd into 32-way bucketed
// per-layer accumulators (8192 addrs -> ~195 ops/addr, no hotspot).
// Visibility to gemm(l+1)/pool via kernel-launch ordering; no threadfence.
__global__ void __launch_bounds__(512) aggregate_kernel(int l) {
    __shared__ float2 sv[512];
    int t = threadIdx.x;
    int node = blockIdx.x * 8 + (t >> 6);   // grid exact: AGB*8 == NN
    int c = t & 63;
    int s = g_off[node], e = g_off[node + 1];
    float ax0 = 0.f, ay0 = 0.f, ax1 = 0.f, ay1 = 0.f;
    int j = s;
    for (; j + 1 < e; j += 2) {
        int2 e0 = g_edge[j];
        int2 e1 = g_edge[j + 1];
        unsigned int u0 = g_hb[e0.x * 64 + c];
        unsigned int u1 = g_hb[e1.x * 64 + c];
        float2 f0 = __bfloat1622float2(*(__nv_bfloat162*)&u0);
        float2 f1 = __bfloat1622float2(*(__nv_bfloat162*)&u1);
        float w0 = __int_as_float(e0.y);
        float w1 = __int_as_float(e1.y);
        ax0 += w0 * f0.x; ay0 += w0 * f0.y;
        ax1 += w1 * f1.x; ay1 += w1 * f1.y;
    }
    if (j < e) {
        int2 e0 = g_edge[j];
        unsigned int u0 = g_hb[e0.x * 64 + c];
        float2 f0 = __bfloat1622float2(*(__nv_bfloat162*)&u0);
        float w0 = __int_as_float(e0.y);
        ax0 += w0 * f0.x; ay0 += w0 * f0.y;
    }
    float r0 = ax0 + ax1, r1 = ay0 + ay1;
    __nv_bfloat162 b = __floats2bfloat162_rn(r0, r1);
    g_aggb[node * 64 + c] = *(unsigned int*)&b;

    // BN partials from pre-rounding fp32 values
    sv[t] = make_float2(r0, r1);
    __syncthreads();
    if (t < 128) {
        float s1 = 0.f, s2 = 0.f;
        #pragma unroll
        for (int gsl = 0; gsl < 8; gsl++) {
            float2 v2 = sv[gsl * 64 + (t >> 1)];
            float v = (t & 1) ? v2.y : v2.x;
            s1 += v; s2 += v * v;
        }
        int bkt = blockIdx.x & 31;
        atomicAdd(&g_bns[(l * 64 + bkt) * 128 + t], s1);
        atomicAdd(&g_bns[(l * 64 + 32 + bkt) * 128 + t], s2);
    }
}

// ---------------- pool + head (layer-2 BN inline; resets g_cursor only) -----
__global__ void __launch_bounds__(512) pool_head_kernel(const void* batch_raw,
                                                        const float* __restrict__ gam,
                                                        const float* __restrict__ bet,
                                                        const float* __restrict__ Wh,
                                                        const float* __restrict__ bh,
                                                        float* __restrict__ out) {
    __shared__ float part[512];
    __shared__ float pooled[CC];
    __shared__ float s_sc[128], s_sh[128];
    __shared__ int sb[2];
    int g = blockIdx.x;
    int t = threadIdx.x;
    int c = t & 127;
    int sub = t >> 7;  // 0..3
    bn_consts(2, gam, bet, s_sc, s_sh);
    if (t >= 128 && t < 130) {
        // batch dtype from the tail: word [NN-1] readable either width;
        // int64 -> high word of elem 24999 (0) with word [NN-2] nonzero
        // w.h.p.; int32 -> batch[NN-1] ~ 63 nonzero w.h.p.
        const int* b32 = (const int*)batch_raw;
        int bis64 = (b32[NN - 1] == 0 && b32[NN - 2] != 0) ? 1 : 0;
        int target = g + (t - 128);
        int lo = 0, hi = NN;
        if (bis64) {
            const long long* b = (const long long*)batch_raw;
            while (lo < hi) { int mid = (lo + hi) >> 1; if (b[mid] < (long long)target) lo = mid + 1; else hi = mid; }
        } else {
            while (lo < hi) { int mid = (lo + hi) >> 1; if (b32[mid] < target) lo = mid + 1; else hi = mid; }
        }
        sb[t - 128] = lo;
    }
    __syncthreads();
    int s = sb[0], e = sb[1];
    float sc = s_sc[c], sh = s_sh[c];
    float a = 0.f;
    for (int r = s + sub; r < e; r += 4) {
        unsigned int w = g_aggb[r * 64 + (c >> 1)];
        float2 f = __bfloat1622float2(*(__nv_bfloat162*)&w);
        float v = (c & 1) ? f.y : f.x;
        a += fmaxf(fmaf(v, sc, sh), 0.f);
    }
    part[t] = a;
    __syncthreads();
    if (t < 128) {
        float cnt = (float)(e - s);
        pooled[t] = (part[t] + part[t + 128] + part[t + 256] + part[t + 384])
                    / fmaxf(cnt, 1.0f);
    }
    __syncthreads();
    if (t < 8) {
        float o = bh[t];
        #pragma unroll 8
        for (int k = 0; k < CC; k++) o += pooled[k] * Wh[k * 8 + t];
        out[g * 8 + t] = o;
    }
    // reset CSR cursor for the next replay (pool never reads it -> no race;
    // g_bns is deliberately NOT reset here — scan1 zeroes it next replay)
    for (int i = g * 512 + t; i < NN; i += NG * 512) g_cursor[i] = 0;
}

// ---------------- launch ----------------
extern "C" void kernel_launch(void* const* d_in, const int* in_sizes, int n_in,
                              void* d_out, int out_size) {
    const float* x  = (const float*)d_in[0];
    const void*  ei = d_in[1];
    const void*  batch = d_in[2];
    const float* W[3]  = { (const float*)d_in[3],  (const float*)d_in[7],  (const float*)d_in[11] };
    const float* gg[3] = { (const float*)d_in[5],  (const float*)d_in[9],  (const float*)d_in[13] };
    const float* be[3] = { (const float*)d_in[6],  (const float*)d_in[10], (const float*)d_in[14] };
    const float* Wh = (const float*)d_in[15];
    const float* bh = (const float*)d_in[16];
    float* out = (float*)d_out;

    const int EB = (NE + 255) / 256;   // 2344

    cudaFuncSetAttribute(gemm_kernel,
                         cudaFuncAttributeMaxDynamicSharedMemorySize, GEMM_SMEM);

    prep_kernel<<<EB, 256>>>(ei);
    scan1_kernel<<<NB, 256>>>();
    scan23_kernel<<<NB, 256>>>();
    fill_kernel<<<EB, 256>>>(ei);

    for (int l = 0; l < 3; l++) {
        // gemm(l) consumes layer l-1 BN buckets (l>0); gam/bet of layer l-1
        gemm_kernel<<<(NN + 127) / 128, 256, GEMM_SMEM>>>(
            x, W[l], l > 0 ? gg[l - 1] : gg[0], l > 0 ? be[l - 1] : be[0], l);
        aggregate_kernel<<<AGB, 512>>>(l);
    }

    pool_head_kernel<<<NG, 512>>>(batch, gg[2], be[2], Wh, bh, out);
}

// round 17
// speedup vs baseline: 1.5727x; 1.0187x over previous
#include <cuda_runtime.h>
#include <cuda_bf16.h>

#define NN 50000
#define NE 600000
#define CC 128
#define NG 64
#define EPSV 1e-5f
#define NB 196      // ceil(NN/256)
#define AGB 3125    // NN/16 aggregate blocks
#define GEMM_SMEM (2 * 128 * 68 * 4)   // As + Wt, 68 words/row (8-bf16 pad)

// ---------------- scratch (device globals; zero-initialized .bss) -----------
__device__ unsigned int g_hb[NN * 64];    // GEMM out, bf16x2 (2 ch / uint)
__device__ unsigned int g_aggb[NN * 64];  // aggregated messages, bf16x2
__device__ int   g_degi[NN];              // zeroed by scan1 after use
__device__ float g_dinv[NN];
__device__ int   g_off[NN + 1];
__device__ int   g_cursor[NN];            // zeroed by pool_head after use
__device__ int   g_bsum[256];
__device__ int2  g_edge[NE];              // CSR payload: {src, f32bits(weight)}
// BN bucket accumulators: [layer][sum bkt 0-31 | sumsq bkt 32-63][128 ch].
// Zeroed by scan1 at the START of each replay (before any aggregate writes,
// after the previous replay's pool_head consumed them) -> no read/reset race.
__device__ float g_bns[3 * 64 * 128];

// per-block edge_index dtype detection (int64 little-endian: interleaved high
// words all zero for values < 2^31; int32 random in [0,NN): false-positive
// prob ~(1/NN)^16 ~ 0). Identical answer every block.
__device__ __forceinline__ int detect_is64(const int* ei32, int* sflag) {
    if (threadIdx.x == 0) {
        int z = 1;
        #pragma unroll
        for (int k = 0; k < 16; k++)
            if (ei32[2 * k + 1] != 0) z = 0;
        *sflag = z;
    }
    __syncthreads();
    return *sflag;
}

// ---------------- degree count (g_degi starts zero; scan1 re-zeros) ---------
__global__ void prep_kernel(const void* ei_raw) {
    __shared__ int sflag;
    int is64 = detect_is64((const int*)ei_raw, &sflag);
    int e = blockIdx.x * blockDim.x + threadIdx.x;
    if (e >= NE) return;
    int d;
    if (is64) d = (int)((const long long*)ei_raw)[NE + e];
    else      d = ((const int*)ei_raw)[NE + e];
    atomicAdd(&g_degi[d], 1);
}

// ---------------- CSR build: scan (dinv fused; zeroes degi + BN buckets) ----
__global__ void scan1_kernel() {
    __shared__ int sh[256];
    int t = threadIdx.x;
    int i = blockIdx.x * 256 + t;
    int v = (i < NN) ? g_degi[i] : 0;
    if (i < NN) {
        g_dinv[i] = (v > 0) ? rsqrtf((float)v) : 0.0f;
        g_degi[i] = 0;                     // reset for next replay
    }
    if (i < 3 * 64 * 128) g_bns[i] = 0.f;  // fresh buckets for this replay
    sh[t] = v;
    __syncthreads();
    #pragma unroll
    for (int off = 1; off < 256; off <<= 1) {
        int tmp = (t >= off) ? sh[t - off] : 0;
        __syncthreads();
        sh[t] += tmp;
        __syncthreads();
    }
    if (i < NN) g_off[i] = sh[t] - v;      // exclusive within block
    if (t == 255) g_bsum[blockIdx.x] = sh[255];
}

__global__ void scan23_kernel() {
    __shared__ int sh[256];
    int t = threadIdx.x;
    int v = (t < NB) ? g_bsum[t] : 0;
    sh[t] = v;
    __syncthreads();
    #pragma unroll
    for (int off = 1; off < 256; off <<= 1) {
        int tmp = (t >= off) ? sh[t - off] : 0;
        __syncthreads();
        sh[t] += tmp;
        __syncthreads();
    }
    int base = (blockIdx.x == 0) ? 0 : sh[blockIdx.x - 1];  // exclusive prefix
    int i = blockIdx.x * 256 + t;
    if (i < NN) g_off[i] += base;
    if (i == 0) g_off[NN] = NE;
}

__global__ void fill_kernel(const void* ei_raw) {
    __shared__ int sflag;
    int is64 = detect_is64((const int*)ei_raw, &sflag);
    int e = blockIdx.x * blockDim.x + threadIdx.x;
    if (e >= NE) return;
    int s, d;
    if (is64) {
        const long long* p = (const long long*)ei_raw;
        s = (int)p[e]; d = (int)p[NE + e];
    } else {
        const int* p = (const int*)ei_raw;
        s = p[e]; d = p[NE + e];
    }
    float w = g_dinv[s] * g_dinv[d];
    int p2 = atomicAdd(&g_cursor[d], 1);
    g_edge[g_off[d] + p2] = make_int2(s, __float_as_int(w));
}

// compute BN scale/shift for layer lm1 from its buckets into smem (redundant
// per block — the scan23 trick). 128 threads participate; callers sync after.
__device__ __forceinline__ void bn_consts(int lm1, const float* gam,
                                          const float* bet,
                                          float* s_sc, float* s_sh) {
    int t = threadIdx.x;
    if (t < 128) {
        float ts = 0.f, ts2 = 0.f;
        #pragma unroll
        for (int b = 0; b < 32; b++) {
            ts  += g_bns[(lm1 * 64 + b) * 128 + t];
            ts2 += g_bns[(lm1 * 64 + 32 + b) * 128 + t];
        }
        float mu = ts * (1.0f / NN);
        float var = fmaxf(ts2 * (1.0f / NN) - mu * mu, 0.f);
        float sc = gam[t] * rsqrtf(var + EPSV);
        s_sc[t] = sc;
        s_sh[t] = bet[t] - mu * sc;
    }
}

// ---------------- tensor-core GEMM: [NN,128] @ [128,128] -> g_hb ------------
// mma.sync.m16n8k16 bf16 x bf16 -> f32. Block tile 128x128, K=128 resident.
// l>0: A = relu(bf16(g_aggb) * scale + shift), BN consts computed inline from
// layer l-1 buckets. l==0: A = Xext fp32 -> bf16.
__device__ __forceinline__ void mma16816(float* d, const unsigned int* a,
                                         unsigned int b0, unsigned int b1) {
    asm volatile(
        "mma.sync.aligned.m16n8k16.row.col.f32.bf16.bf16.f32 "
        "{%0,%1,%2,%3}, {%4,%5,%6,%7}, {%8,%9}, {%0,%1,%2,%3};\n"
        : "+f"(d[0]), "+f"(d[1]), "+f"(d[2]), "+f"(d[3])
        : "r"(a[0]), "r"(a[1]), "r"(a[2]), "r"(a[3]), "r"(b0), "r"(b1));
}

__global__ void __launch_bounds__(256) gemm_kernel(const float* __restrict__ Xext,
                                                   const float* __restrict__ W,
                                                   const float* __restrict__ gam,
                                                   const float* __restrict__ bet,
                                                   int l) {
    extern __shared__ unsigned int smem_u[];
    unsigned int* As = smem_u;              // [128 rows][68 words] bf16x2, k-pairs
    unsigned int* Wt = smem_u + 128 * 68;   // [128 n-rows][68 words] k-pairs
    __shared__ float s_sc[128], s_sh[128];
    int tid = threadIdx.x;
    int m0 = blockIdx.x * 128;

    if (l > 0) bn_consts(l - 1, gam, bet, s_sc, s_sh);

    // Wt load: item = (kp, n); W[2kp][n], W[2kp+1][n] -> bf16x2 at Wt[n][kp].
    #pragma unroll 4
    for (int it = 0; it < 32; it++) {
        int item = tid + 256 * it;          // 8192 items
        int n = item & 127, kp = item >> 7;
        float w0 = W[(2 * kp) * 128 + n];
        float w1 = W[(2 * kp + 1) * 128 + n];
        __nv_bfloat162 b = __floats2bfloat162_rn(w0, w1);
        Wt[n * 68 + kp] = *(unsigned int*)&b;
    }
    __syncthreads();   // s_sc/s_sh ready before A-load uses them

    #pragma unroll 4
    for (int it = 0; it < 16; it++) {
        int f = tid + 256 * it;             // 4096 items (4 channels each)
        int row = f >> 5, c4 = f & 31;
        int grow = m0 + row;
        float4 v = make_float4(0.f, 0.f, 0.f, 0.f);
        if (grow < NN) {
            if (l > 0) {
                uint2 pq = *(const uint2*)(g_aggb + grow * 64 + c4 * 2);
                float2 f01 = __bfloat1622float2(*(__nv_bfloat162*)&pq.x);
                float2 f23 = __bfloat1622float2(*(__nv_bfloat162*)&pq.y);
                int col = c4 * 4;
                v.x = fmaxf(fmaf(f01.x, s_sc[col],     s_sh[col]),     0.f);
                v.y = fmaxf(fmaf(f01.y, s_sc[col + 1], s_sh[col + 1]), 0.f);
                v.z = fmaxf(fmaf(f23.x, s_sc[col + 2], s_sh[col + 2]), 0.f);
                v.w = fmaxf(fmaf(f23.y, s_sc[col + 3], s_sh[col + 3]), 0.f);
            } else {
                v = *(const float4*)(Xext + grow * CC + c4 * 4);
            }
        }
        __nv_bfloat162 p0 = __floats2bfloat162_rn(v.x, v.y);
        __nv_bfloat162 p1 = __floats2bfloat162_rn(v.z, v.w);
        As[row * 68 + c4 * 2]     = *(unsigned int*)&p0;
        As[row * 68 + c4 * 2 + 1] = *(unsigned int*)&p1;
    }
    __syncthreads();

    int lane = tid & 31;
    int w = tid >> 5;
    int warpM = w >> 1, warpN = w & 1;
    int rq = lane >> 2, lq = lane & 3;

    float acc[2][8][4];
    #pragma unroll
    for (int ma = 0; ma < 2; ma++)
        #pragma unroll
        for (int na = 0; na < 8; na++)
            #pragma unroll
            for (int q = 0; q < 4; q++) acc[ma][na][q] = 0.f;

    #pragma unroll
    for (int k0 = 0; k0 < 8; k0++) {
        int cp = k0 * 8 + lq;
        unsigned int a[2][4];
        #pragma unroll
        for (int ma = 0; ma < 2; ma++) {
            int r = warpM * 32 + ma * 16 + rq;
            a[ma][0] = As[r * 68 + cp];
            a[ma][1] = As[(r + 8) * 68 + cp];
            a[ma][2] = As[r * 68 + cp + 4];
            a[ma][3] = As[(r + 8) * 68 + cp + 4];
        }
        #pragma unroll
        for (int na = 0; na < 8; na++) {
            int n = warpN * 64 + na * 8 + rq;
            unsigned int b0 = Wt[n * 68 + cp];
            unsigned int b1 = Wt[n * 68 + cp + 4];
            mma16816(acc[0][na], a[0], b0, b1);
            mma16816(acc[1][na], a[1], b0, b1);
        }
    }

    #pragma unroll
    for (int ma = 0; ma < 2; ma++) {
        int r = m0 + warpM * 32 + ma * 16 + rq;
        #pragma unroll
        for (int na = 0; na < 8; na++) {
            int cu = warpN * 32 + na * 4 + lq;
            if (r < NN) {
                __nv_bfloat162 p = __floats2bfloat162_rn(acc[ma][na][0], acc[ma][na][1]);
                g_hb[r * 64 + cu] = *(unsigned int*)&p;
            }
            if (r + 8 < NN) {
                __nv_bfloat162 p = __floats2bfloat162_rn(acc[ma][na][2], acc[ma][na][3]);
                g_hb[(r + 8) * 64 + cu] = *(unsigned int*)&p;
            }
        }
    }
}

// ---------------- aggregation: 32 thr/node, uint2 loads + BN partials -------
// 32 threads/node, 4 channels each (uint2 = 8B load); 16 nodes / 512-thr
// block; grid = AGB (3125*16 == NN). Same 256B/row coalescing, half the LDG
// count vs 64-thr layout -> double bytes in flight at equal MLP.
__global__ void __launch_bounds__(512) aggregate_kernel(int l) {
    __shared__ float4 sv[512];
    int t = threadIdx.x;
    int node = blockIdx.x * 16 + (t >> 5);
    int c = t & 31;                         // uint2 index; channels 4c..4c+3
    int s = g_off[node], e = g_off[node + 1];
    float a0 = 0.f, a1 = 0.f, a2 = 0.f, a3 = 0.f;
    float b0 = 0.f, b1 = 0.f, b2 = 0.f, b3 = 0.f;
    int j = s;
    for (; j + 1 < e; j += 2) {
        int2 e0 = g_edge[j];
        int2 e1 = g_edge[j + 1];
        uint2 u0 = *(const uint2*)(g_hb + e0.x * 64 + 2 * c);
        uint2 u1 = *(const uint2*)(g_hb + e1.x * 64 + 2 * c);
        float w0 = __int_as_float(e0.y);
        float w1 = __int_as_float(e1.y);
        float2 p00 = __bfloat1622float2(*(__nv_bfloat162*)&u0.x);
        float2 p01 = __bfloat1622float2(*(__nv_bfloat162*)&u0.y);
        float2 p10 = __bfloat1622float2(*(__nv_bfloat162*)&u1.x);
        float2 p11 = __bfloat1622float2(*(__nv_bfloat162*)&u1.y);
        a0 += w0 * p00.x; a1 += w0 * p00.y; a2 += w0 * p01.x; a3 += w0 * p01.y;
        b0 += w1 * p10.x; b1 += w1 * p10.y; b2 += w1 * p11.x; b3 += w1 * p11.y;
    }
    if (j < e) {
        int2 e0 = g_edge[j];
        uint2 u0 = *(const uint2*)(g_hb + e0.x * 64 + 2 * c);
        float w0 = __int_as_float(e0.y);
        float2 p00 = __bfloat1622float2(*(__nv_bfloat162*)&u0.x);
        float2 p01 = __bfloat1622float2(*(__nv_bfloat162*)&u0.y);
        a0 += w0 * p00.x; a1 += w0 * p00.y; a2 += w0 * p01.x; a3 += w0 * p01.y;
    }
    float r0 = a0 + b0, r1 = a1 + b1, r2 = a2 + b2, r3 = a3 + b3;
    __nv_bfloat162 q0 = __floats2bfloat162_rn(r0, r1);
    __nv_bfloat162 q1 = __floats2bfloat162_rn(r2, r3);
    *(uint2*)(g_aggb + node * 64 + 2 * c) =
        make_uint2(*(unsigned int*)&q0, *(unsigned int*)&q1);

    // BN partials from pre-rounding fp32: channel t -> thread (t>>2) of each
    // of the 16 node-groups, component t&3.
    sv[t] = make_float4(r0, r1, r2, r3);
    __syncthreads();
    if (t < 128) {
        int comp = t & 3;
        float s1 = 0.f, s2 = 0.f;
        #pragma unroll
        for (int grp = 0; grp < 16; grp++) {
            float4 v4 = sv[grp * 32 + (t >> 2)];
            float v = (comp == 0) ? v4.x : (comp == 1) ? v4.y
                      : (comp == 2) ? v4.z : v4.w;
            s1 += v; s2 += v * v;
        }
        int bkt = blockIdx.x & 31;
        atomicAdd(&g_bns[(l * 64 + bkt) * 128 + t], s1);
        atomicAdd(&g_bns[(l * 64 + 32 + bkt) * 128 + t], s2);
    }
}

// ---------------- pool + head (layer-2 BN inline; resets g_cursor only) -----
__global__ void __launch_bounds__(512) pool_head_kernel(const void* batch_raw,
                                                        const float* __restrict__ gam,
                                                        const float* __restrict__ bet,
                                                        const float* __restrict__ Wh,
                                                        const float* __restrict__ bh,
                                                        float* __restrict__ out) {
    __shared__ float part[512];
    __shared__ float pooled[CC];
    __shared__ float s_sc[128], s_sh[128];
    __shared__ int sb[2];
    int g = blockIdx.x;
    int t = threadIdx.x;
    int c = t & 127;
    int sub = t >> 7;  // 0..3
    bn_consts(2, gam, bet, s_sc, s_sh);
    if (t >= 128 && t < 130) {
        // batch dtype from the tail: word [NN-1] readable either width;
        // int64 -> high word of elem 24999 (0) with word [NN-2] nonzero
        // w.h.p.; int32 -> batch[NN-1] ~ 63 nonzero w.h.p.
        const int* b32 = (const int*)batch_raw;
        int bis64 = (b32[NN - 1] == 0 && b32[NN - 2] != 0) ? 1 : 0;
        int target = g + (t - 128);
        int lo = 0, hi = NN;
        if (bis64) {
            const long long* b = (const long long*)batch_raw;
            while (lo < hi) { int mid = (lo + hi) >> 1; if (b[mid] < (long long)target) lo = mid + 1; else hi = mid; }
        } else {
            while (lo < hi) { int mid = (lo + hi) >> 1; if (b32[mid] < target) lo = mid + 1; else hi = mid; }
        }
        sb[t - 128] = lo;
    }
    __syncthreads();
    int s = sb[0], e = sb[1];
    float sc = s_sc[c], sh = s_sh[c];
    float a = 0.f;
    for (int r = s + sub; r < e; r += 4) {
        unsigned int w = g_aggb[r * 64 + (c >> 1)];
        float2 f = __bfloat1622float2(*(__nv_bfloat162*)&w);
        float v = (c & 1) ? f.y : f.x;
        a += fmaxf(fmaf(v, sc, sh), 0.f);
    }
    part[t] = a;
    __syncthreads();
    if (t < 128) {
        float cnt = (float)(e - s);
        pooled[t] = (part[t] + part[t + 128] + part[t + 256] + part[t + 384])
                    / fmaxf(cnt, 1.0f);
    }
    __syncthreads();
    if (t < 8) {
        float o = bh[t];
        #pragma unroll 8
        for (int k = 0; k < CC; k++) o += pooled[k] * Wh[k * 8 + t];
        out[g * 8 + t] = o;
    }
    // reset CSR cursor for the next replay (pool never reads it -> no race;
    // g_bns is deliberately NOT reset here — scan1 zeroes it next replay)
    for (int i = g * 512 + t; i < NN; i += NG * 512) g_cursor[i] = 0;
}

// ---------------- launch ----------------
extern "C" void kernel_launch(void* const* d_in, const int* in_sizes, int n_in,
                              void* d_out, int out_size) {
    const float* x  = (const float*)d_in[0];
    const void*  ei = d_in[1];
    const void*  batch = d_in[2];
    const float* W[3]  = { (const float*)d_in[3],  (const float*)d_in[7],  (const float*)d_in[11] };
    const float* gg[3] = { (const float*)d_in[5],  (const float*)d_in[9],  (const float*)d_in[13] };
    const float* be[3] = { (const float*)d_in[6],  (const float*)d_in[10], (const float*)d_in[14] };
    const float* Wh = (const float*)d_in[15];
    const float* bh = (const float*)d_in[16];
    float* out = (float*)d_out;

    const int EB = (NE + 255) / 256;   // 2344

    cudaFuncSetAttribute(gemm_kernel,
                         cudaFuncAttributeMaxDynamicSharedMemorySize, GEMM_SMEM);

    prep_kernel<<<EB, 256>>>(ei);
    scan1_kernel<<<NB, 256>>>();
    scan23_kernel<<<NB, 256>>>();
    fill_kernel<<<EB, 256>>>(ei);

    for (int l = 0; l < 3; l++) {
        // gemm(l) consumes layer l-1 BN buckets (l>0); gam/bet of layer l-1
        gemm_kernel<<<(NN + 127) / 128, 256, GEMM_SMEM>>>(
            x, W[l], l > 0 ? gg[l - 1] : gg[0], l > 0 ? be[l - 1] : be[0], l);
        aggregate_kernel<<<AGB, 512>>>(l);
    }

    pool_head_kernel<<<NG, 512>>>(batch, gg[2], be[2], Wh, bh, out);
}